// round 2
// baseline (speedup 1.0000x reference)
#include <cuda_runtime.h>
#include <math.h>

#define B 16
#define C 256
#define H 128
#define W 128
#define HW (H*W)
#define R 16

// Scratch (allocation-free: __device__ globals)
__device__ float g_avg[B*C];
__device__ float g_max[B*C];
__device__ float g_wch[B*C];
__device__ float g_cat[B*2*HW];   // [b][0]=maxmap, [b][1]=avgmap
__device__ float g_ws[B*HW];

// ---------------- K1: per-(b,c) mean & max over H,W ----------------
__global__ void k_reduce_hw(const float* __restrict__ x) {
    int bc = blockIdx.x;                 // 0..B*C-1
    const float4* xp = (const float4*)(x + (size_t)bc * HW);
    float s = 0.f, m = -INFINITY;
    #pragma unroll 4
    for (int i = threadIdx.x; i < HW/4; i += blockDim.x) {
        float4 v = xp[i];
        s += (v.x + v.y) + (v.z + v.w);
        m = fmaxf(m, fmaxf(fmaxf(v.x, v.y), fmaxf(v.z, v.w)));
    }
    #pragma unroll
    for (int o = 16; o; o >>= 1) {
        s += __shfl_xor_sync(0xffffffffu, s, o);
        m = fmaxf(m, __shfl_xor_sync(0xffffffffu, m, o));
    }
    __shared__ float ss[8], sm[8];
    int w = threadIdx.x >> 5, l = threadIdx.x & 31;
    if (l == 0) { ss[w] = s; sm[w] = m; }
    __syncthreads();
    if (threadIdx.x == 0) {
        for (int i = 1; i < (int)(blockDim.x >> 5); i++) { s += ss[i]; m = fmaxf(m, sm[i]); }
        g_avg[bc] = s * (1.f / HW);
        g_max[bc] = m;
    }
}

// ---------------- K2: channel MLP -> wch ----------------
__global__ void k_mlp(const float* __restrict__ w1, const float* __restrict__ b1,
                      const float* __restrict__ w2, const float* __restrict__ b2) {
    int b = blockIdx.x;
    int t = threadIdx.x;                 // 0..255 = channel
    __shared__ float s_avg[C], s_mx[C], s_h[R];
    s_avg[t] = g_avg[b*C + t];
    s_mx[t]  = g_max[b*C + t];
    __syncthreads();
    if (t < R) {
        float ha = b1[t], hm = b1[t];
        #pragma unroll 8
        for (int c = 0; c < C; c++) {
            float w = w1[t*C + c];
            ha += w * s_avg[c];
            hm += w * s_mx[c];
        }
        s_h[t] = fmaxf(ha, 0.f) + fmaxf(hm, 0.f);
    }
    __syncthreads();
    float o = 2.f * b2[t];
    #pragma unroll
    for (int r = 0; r < R; r++) o += w2[t*R + r] * s_h[r];
    g_wch[b*C + t] = 1.f / (1.f + expf(-o));
}

// ---------------- K3: cat = [max_c(wch*x), mean_c(wch*x)] ----------------
__global__ void k_cat(const float* __restrict__ x) {
    int b  = blockIdx.y;
    int p4 = blockIdx.x * blockDim.x + threadIdx.x;   // float4 index within HW
    __shared__ float sw[C];
    for (int i = threadIdx.x; i < C; i += blockDim.x) sw[i] = g_wch[b*C + i];
    __syncthreads();
    const float4* xb = (const float4*)(x + (size_t)b * C * HW);
    float4 s = make_float4(0.f, 0.f, 0.f, 0.f);
    float4 m = make_float4(-INFINITY, -INFINITY, -INFINITY, -INFINITY);
    #pragma unroll 4
    for (int c = 0; c < C; c++) {
        float4 v = __ldg(&xb[(size_t)c * (HW/4) + p4]);
        float w = sw[c];
        float a0 = w*v.x, a1 = w*v.y, a2 = w*v.z, a3 = w*v.w;
        s.x += a0; s.y += a1; s.z += a2; s.w += a3;
        m.x = fmaxf(m.x, a0); m.y = fmaxf(m.y, a1);
        m.z = fmaxf(m.z, a2); m.w = fmaxf(m.w, a3);
    }
    const float inv = 1.f / C;
    s.x *= inv; s.y *= inv; s.z *= inv; s.w *= inv;
    ((float4*)(g_cat + (size_t)b*2*HW))[p4]      = m;   // maxmap (ch 0)
    ((float4*)(g_cat + (size_t)b*2*HW + HW))[p4] = s;   // avgmap (ch 1)
}

// ---------------- K4: offsets conv + deform conv + BN + sigmoid -> ws ----------------
__global__ void k_deform(const float* __restrict__ off_w, const float* __restrict__ off_b,
                         const float* __restrict__ dc_w,  const float* __restrict__ dc_b,
                         const float* __restrict__ bn_gamma, const float* __restrict__ bn_beta,
                         const float* __restrict__ bn_mean,  const float* __restrict__ bn_var) {
    __shared__ float s_ow[18*2*9], s_ob[18], s_dw[18];
    for (int t = threadIdx.x; t < 18*2*9; t += blockDim.x) s_ow[t] = off_w[t];
    if (threadIdx.x < 18) {
        s_ob[threadIdx.x] = off_b[threadIdx.x];
        s_dw[threadIdx.x] = dc_w[threadIdx.x];   // [1,2,3,3] -> [ci*9+k]
    }
    __syncthreads();

    int p  = blockIdx.x * blockDim.x + threadIdx.x;  // global pixel
    int b  = p >> 14;
    int hw = p & (HW - 1);
    int i  = hw >> 7;
    int j  = hw & (W - 1);

    const float* c0 = g_cat + (size_t)b*2*HW;        // maxmap
    const float* c1 = c0 + HW;                       // avgmap

    // 3x3 neighborhoods of both cat channels (zero-padded)
    float n0[9], n1[9];
    #pragma unroll
    for (int u = 0; u < 3; u++) {
        #pragma unroll
        for (int v = 0; v < 3; v++) {
            int yy = i + u - 1, xx = j + v - 1;
            bool ok = (yy >= 0) & (yy < H) & (xx >= 0) & (xx < W);
            int idx = yy*W + xx;
            n0[u*3+v] = ok ? c0[idx] : 0.f;
            n1[u*3+v] = ok ? c1[idx] : 0.f;
        }
    }

    // 18 offset channels
    float off[18];
    #pragma unroll
    for (int t = 0; t < 18; t++) {
        float a = s_ob[t];
        const float* w0 = &s_ow[t*18];
        #pragma unroll
        for (int q = 0; q < 9; q++) a += w0[q] * n0[q];
        #pragma unroll
        for (int q = 0; q < 9; q++) a += w0[9+q] * n1[q];
        off[t] = a;
    }

    float acc = __ldg(dc_b);
    #pragma unroll
    for (int k = 0; k < 9; k++) {
        float py = (float)i + (float)(k/3 - 1) + off[2*k];
        float px = (float)j + (float)(k%3 - 1) + off[2*k + 1];
        float y0 = floorf(py), x0 = floorf(px);
        float wy = py - y0, wx = px - x0;
        int y0i = (int)y0, x0i = (int)x0;

        float s0 = 0.f, s1 = 0.f;
        #pragma unroll
        for (int dy = 0; dy < 2; dy++) {
            #pragma unroll
            for (int dx = 0; dx < 2; dx++) {
                int yi = y0i + dy, xi = x0i + dx;
                bool ok = (yi >= 0) & (yi < H) & (xi >= 0) & (xi < W);
                int yc = min(max(yi, 0), H-1);
                int xc = min(max(xi, 0), W-1);
                int idx = yc*W + xc;
                float v0 = ok ? __ldg(&c0[idx]) : 0.f;
                float v1 = ok ? __ldg(&c1[idx]) : 0.f;
                float wgt = (dy ? wy : 1.f - wy) * (dx ? wx : 1.f - wx);
                s0 += v0 * wgt;
                s1 += v1 * wgt;
            }
        }
        acc += s0 * s_dw[k] + s1 * s_dw[9 + k];
    }

    float inv = __ldg(bn_gamma) * rsqrtf(__ldg(bn_var) + 1e-5f);
    float d = (acc - __ldg(bn_mean)) * inv + __ldg(bn_beta);
    g_ws[b*HW + hw] = 1.f / (1.f + expf(-d));
}

// ---------------- K5: out = x * (1 + wch*ws) ----------------
__global__ void k_final(const float* __restrict__ x, float* __restrict__ out) {
    size_t i4 = (size_t)blockIdx.x * blockDim.x + threadIdx.x;  // float4 index
    size_t e  = i4 << 2;
    int b  = (int)(e >> 22);            // C*HW = 2^22
    int c  = (int)(e >> 14) & (C - 1);
    int hw = (int)e & (HW - 1);
    float w = g_wch[b*C + c];
    float4 xv  = ((const float4*)x)[i4];
    float4 wsv = __ldg((const float4*)(g_ws + (size_t)b*HW + hw));
    float4 o;
    o.x = xv.x * fmaf(w, wsv.x, 1.f);
    o.y = xv.y * fmaf(w, wsv.y, 1.f);
    o.z = xv.z * fmaf(w, wsv.z, 1.f);
    o.w = xv.w * fmaf(w, wsv.w, 1.f);
    ((float4*)out)[i4] = o;
}

extern "C" void kernel_launch(void* const* d_in, const int* in_sizes, int n_in,
                              void* d_out, int out_size) {
    const float* x     = (const float*)d_in[0];
    const float* w1    = (const float*)d_in[1];
    const float* b1    = (const float*)d_in[2];
    const float* w2    = (const float*)d_in[3];
    const float* b2    = (const float*)d_in[4];
    const float* off_w = (const float*)d_in[5];
    const float* off_b = (const float*)d_in[6];
    const float* dc_w  = (const float*)d_in[7];
    const float* dc_b  = (const float*)d_in[8];
    const float* bng   = (const float*)d_in[9];
    const float* bnb   = (const float*)d_in[10];
    const float* bnm   = (const float*)d_in[11];
    const float* bnv   = (const float*)d_in[12];
    float* out = (float*)d_out;

    k_reduce_hw<<<B*C, 256>>>(x);
    k_mlp<<<B, C>>>(w1, b1, w2, b2);
    {
        dim3 grid(HW/(128*4), B);
        k_cat<<<grid, 128>>>(x);
    }
    k_deform<<<(B*HW)/256, 256>>>(off_w, off_b, dc_w, dc_b, bng, bnb, bnm, bnv);
    k_final<<<(size_t)(B*C*HW)/4/256, 256>>>(x, out);
}